// round 12
// baseline (speedup 1.0000x reference)
#include <cuda_runtime.h>
#include <cstdint>

// Scratch: pre[row][32], row = b*512 + t, col = gate*8 + qubit. 33.5 MB.
__device__ float g_pre[512 * 512 * 32];

// ---------------------------------------------------------------------------
__device__ __forceinline__ unsigned long long ffma2(unsigned long long a,
                                                    unsigned long long b,
                                                    unsigned long long c) {
    unsigned long long d;
    asm("fma.rn.f32x2 %0, %1, %2, %3;" : "=l"(d) : "l"(a), "l"(b), "l"(c));
    return d;
}
__device__ __forceinline__ float ex2_approx(float x) {
    float y; asm("ex2.approx.f32 %0, %1;" : "=f"(y) : "f"(x)); return y;
}
__device__ __forceinline__ float rcp_approx(float x) {
    float y; asm("rcp.approx.f32 %0, %1;" : "=f"(y) : "f"(x)); return y;
}

// ---------------------------------------------------------------------------
// Kernel 1: pre[r][c] = sum_k X[r][k]*W[c][k] + bias[c] + theta[c]
//   M=262144, K=256, N=32. Block: 256 thr, 256 rows x 32 cols, occupancy 4.
//   W kept non-duplicated (32 KB); an 8x32 (w,w)-pair slice is re-staged per
//   k-tile into a 4 KB double buffer so total smem = 53 KB -> 4 blocks/SM.
// ---------------------------------------------------------------------------
constexpr int KT  = 8;      // k-tile
constexpr int XSg = 258;    // smem X row stride (floats): 256 rows + pad
// smem floats: master W 8192 | X 2*8*258 = 4128 | dupW 2*8*32 float2 = 1024
constexpr int SMEM_G = (8192 + 4128 + 1024) * 4;   // 53376 B

__global__ void __launch_bounds__(256, 4) gemm_kernel(
    const float* __restrict__ X,
    const float* __restrict__ Wf, const float* __restrict__ bf,
    const float* __restrict__ Wi, const float* __restrict__ bi,
    const float* __restrict__ Wg, const float* __restrict__ bg,
    const float* __restrict__ Wo, const float* __restrict__ bo,
    const float* __restrict__ th)
{
    extern __shared__ float sm[];
    float*  sW  = sm;                                   // [256][32] master
    float*  sX  = sm + 8192;                            // [2][KT][XSg]
    float2* sWD = reinterpret_cast<float2*>(sm + 8192 + 4128); // [2][KT][32]

    const int tid = threadIdx.x;

    // Load master W (row stride 264; first 256 entries = input part).
#pragma unroll
    for (int gi = 0; gi < 4; gi++) {
        const float* Wp = (gi == 0) ? Wf : (gi == 1) ? Wi : (gi == 2) ? Wg : Wo;
        for (int idx = tid; idx < 2048; idx += 256) {
            int k = idx >> 3, nn = idx & 7;
            sW[k * 32 + gi * 8 + nn] = Wp[nn * 264 + k];
        }
    }

    const size_t base0 = (size_t)blockIdx.x * 256;
    const int cg = tid >> 6;      // gate / col group, uniform per warp
    const int rp = tid & 63;      // row-pair id: rows 2rp,2rp+1 (+128)
    const int rq = tid & 127;     // staging row
    const int kc = tid >> 7;      // staging k chunk (0 -> k0..3, 1 -> k4..7)
    const int dk = tid >> 5;      // dup-stage k (0..7)
    const int dc = tid & 31;      // dup-stage col

    float4 ldv[2];
#pragma unroll
    for (int i = 0; i < 2; i++)
        ldv[i] = *reinterpret_cast<const float4*>(
            X + (base0 + rq + 128 * i) * 256 + kc * 4);

    unsigned long long acc[2][8];
#pragma unroll
    for (int j = 0; j < 2; j++)
#pragma unroll
        for (int c = 0; c < 8; c++) acc[j][c] = 0ull;

    // Stage X tile 0 into buffer 0.
#pragma unroll
    for (int i = 0; i < 2; i++) {
        float* dst = sX + kc * 4 * XSg + rq + 128 * i;
        dst[0 * XSg] = ldv[i].x; dst[1 * XSg] = ldv[i].y;
        dst[2 * XSg] = ldv[i].z; dst[3 * XSg] = ldv[i].w;
    }
    __syncthreads();                       // W master + X tile 0 visible

    // Stage dup-W tile 0 into buffer 0.
    {
        float w = sW[dk * 32 + dc];
        sWD[dk * 32 + dc] = make_float2(w, w);
    }
    __syncthreads();                       // dup-W tile 0 visible

    for (int kt = 0; kt < 32; kt++) {
        const int cur = kt & 1, nxt = (kt + 1) & 1;
        if (kt < 31) {
#pragma unroll
            for (int i = 0; i < 2; i++)
                ldv[i] = *reinterpret_cast<const float4*>(
                    X + (base0 + rq + 128 * i) * 256 + (kt + 1) * KT + kc * 4);
            // stage next dup-W slice (reads stable master, writes other buffer)
            float w = sW[((kt + 1) * KT + dk) * 32 + dc];
            sWD[nxt * (KT * 32) + dk * 32 + dc] = make_float2(w, w);
        }

        const float*  bx = sX + cur * (KT * XSg);
        const float2* wk = sWD + cur * (KT * 32) + cg * 8;
#pragma unroll
        for (int kk = 0; kk < KT; kk++) {
            unsigned long long xA = *reinterpret_cast<const unsigned long long*>(
                bx + kk * XSg + 2 * rp);
            unsigned long long xB = *reinterpret_cast<const unsigned long long*>(
                bx + kk * XSg + 2 * rp + 128);
            const ulonglong2* w2 = reinterpret_cast<const ulonglong2*>(wk + kk * 32);
            ulonglong2 wa = w2[0], wb = w2[1];
            acc[0][0] = ffma2(wa.x, xA, acc[0][0]);
            acc[1][0] = ffma2(wa.x, xB, acc[1][0]);
            acc[0][1] = ffma2(wa.y, xA, acc[0][1]);
            acc[1][1] = ffma2(wa.y, xB, acc[1][1]);
            acc[0][2] = ffma2(wb.x, xA, acc[0][2]);
            acc[1][2] = ffma2(wb.x, xB, acc[1][2]);
            acc[0][3] = ffma2(wb.y, xA, acc[0][3]);
            acc[1][3] = ffma2(wb.y, xB, acc[1][3]);
            ulonglong2 wc = w2[2], wd = w2[3];
            acc[0][4] = ffma2(wc.x, xA, acc[0][4]);
            acc[1][4] = ffma2(wc.x, xB, acc[1][4]);
            acc[0][5] = ffma2(wc.y, xA, acc[0][5]);
            acc[1][5] = ffma2(wc.y, xB, acc[1][5]);
            acc[0][6] = ffma2(wd.x, xA, acc[0][6]);
            acc[1][6] = ffma2(wd.x, xB, acc[1][6]);
            acc[0][7] = ffma2(wd.y, xA, acc[0][7]);
            acc[1][7] = ffma2(wd.y, xB, acc[1][7]);
        }

        if (kt < 31) {
            float* dstb = sX + nxt * (KT * XSg);
#pragma unroll
            for (int i = 0; i < 2; i++) {
                float* dst = dstb + kc * 4 * XSg + rq + 128 * i;
                dst[0 * XSg] = ldv[i].x; dst[1 * XSg] = ldv[i].y;
                dst[2 * XSg] = ldv[i].z; dst[3 * XSg] = ldv[i].w;
            }
        }
        __syncthreads();
    }

    // Epilogue: + bias + theta, write 2 row-pairs x 8 cols.
    const float* bptr = (cg == 0) ? bf : (cg == 1) ? bi : (cg == 2) ? bg : bo;
    float bt[8];
#pragma unroll
    for (int c = 0; c < 8; c++) bt[c] = bptr[c] + th[cg * 8 + c];
#pragma unroll
    for (int j = 0; j < 2; j++) {
        size_t pr = base0 + 2 * rp + 128 * j;
        float o0[8], o1[8];
#pragma unroll
        for (int c = 0; c < 8; c++) {
            float2 av = *reinterpret_cast<float2*>(&acc[j][c]);
            o0[c] = av.x + bt[c];
            o1[c] = av.y + bt[c];
        }
        float4* p0 = reinterpret_cast<float4*>(g_pre + pr * 32 + cg * 8);
        float4* p1 = reinterpret_cast<float4*>(g_pre + (pr + 1) * 32 + cg * 8);
        p0[0] = make_float4(o0[0], o0[1], o0[2], o0[3]);
        p0[1] = make_float4(o0[4], o0[5], o0[6], o0[7]);
        p1[0] = make_float4(o1[0], o1[1], o1[2], o1[3]);
        p1[1] = make_float4(o1[4], o1[5], o1[6], o1[7]);
    }
}

// ---------------------------------------------------------------------------
// Kernel 2: LSTM recurrence. 4 warps/block, one batch per warp,
// lane = gate*8 + qubit. Cross-lane traffic via smem + __syncwarp (ping-pong
// buffers), replacing the 20 SHFLs/step that dominated the measured chain.
//   m_k = prod_{j<=k} cos(ang_j) (k>=1),  m_0 = prod_{j=1..7} cos(ang_j)
// ---------------------------------------------------------------------------
__global__ void __launch_bounds__(128) recur_kernel(
    const float* __restrict__ Wf, const float* __restrict__ Wi,
    const float* __restrict__ Wg, const float* __restrict__ Wo,
    float* __restrict__ out)
{
    __shared__ __align__(16) float cbuf[4][2][32];  // cos-1 exchange
    __shared__ __align__(16) float abuf[4][2][32];  // activation exchange
    __shared__ __align__(16) float hbuf[4][2][8];   // hx broadcast

    const int wid  = threadIdx.x >> 5;
    const int lane = threadIdx.x & 31;
    const int b    = blockIdx.x * 4 + wid;
    const int g    = lane >> 3;
    const int n    = lane & 7;
    const int segb = g * 8;
    const float L2E = 1.4426950408889634f;

    const float* Wsel = (g == 0) ? Wf : (g == 1) ? Wi : (g == 2) ? Wg : Wo;
    float wh[8];
#pragma unroll
    for (int h = 0; h < 8; h++) wh[h] = Wsel[n * 264 + 256 + h];

    // Product inclusion mask: n==0 -> j in 1..7, else j in 0..n.
    float incm[8];
#pragma unroll
    for (int j = 0; j < 8; j++)
        incm[j] = ((n == 0) ? (j >= 1) : (j <= n)) ? 1.0f : 0.0f;

    // Activation: f,i,o -> sigmoid(m); g -> tanh(m) = 2*sigmoid(2m)-1.
    const float sA2 = (g == 2) ? (-2.0f * L2E) : (-L2E);
    const float am  = (g == 2) ? 2.0f : 1.0f;
    const float ab  = (g == 2) ? -1.0f : 0.0f;

    float hxa[8];
#pragma unroll
    for (int h = 0; h < 8; h++) hxa[h] = 0.f;
    float cx = 0.f, hx = 0.f;

    const float* pb = g_pre + (size_t)b * 512 * 32 + lane;
    float* ob = out + (size_t)b * 512 * 8 + n;

    float p0 = __ldg(pb);
    float p1 = __ldg(pb + 32);
    for (int t = 0; t < 512; t++) {
        float p2 = __ldg(pb + ((t + 2) & 511) * 32);   // distance-2 prefetch
        const int pp = t & 1;
        float* cb = &cbuf[wid][pp][0];
        float* abf = &abuf[wid][pp][0];
        float* hb = &hbuf[wid][pp][0];

        // angle = pre + W_h . hx  (two parallel fma chains)
        float s1 = p0, s2 = 0.f;
        s1 = fmaf(wh[0], hxa[0], s1);  s2 = fmaf(wh[1], hxa[1], s2);
        s1 = fmaf(wh[2], hxa[2], s1);  s2 = fmaf(wh[3], hxa[3], s2);
        s1 = fmaf(wh[4], hxa[4], s1);  s2 = fmaf(wh[5], hxa[5], s2);
        s1 = fmaf(wh[6], hxa[6], s1);  s2 = fmaf(wh[7], hxa[7], s2);
        float ang = s1 + s2;

        float cm1 = __cosf(ang) - 1.0f;

        // Exchange 1: publish cos-1, read own gate segment's 8 values.
        cb[lane] = cm1;
        __syncwarp();
        float4 c0 = *reinterpret_cast<const float4*>(cb + segb);
        float4 c1 = *reinterpret_cast<const float4*>(cb + segb + 4);

        float v0 = fmaf(incm[0], c0.x, 1.0f);
        float v1 = fmaf(incm[1], c0.y, 1.0f);
        float v2 = fmaf(incm[2], c0.z, 1.0f);
        float v3 = fmaf(incm[3], c0.w, 1.0f);
        float v4 = fmaf(incm[4], c1.x, 1.0f);
        float v5 = fmaf(incm[5], c1.y, 1.0f);
        float v6 = fmaf(incm[6], c1.z, 1.0f);
        float v7 = fmaf(incm[7], c1.w, 1.0f);
        float m = ((v0 * v1) * (v2 * v3)) * ((v4 * v5) * (v6 * v7));

        // a = am * sigmoid(scale*m) + ab
        float e = ex2_approx(m * sA2);
        float r = rcp_approx(1.0f + e);
        float a = fmaf(am, r, ab);

        // Exchange 2: publish activation, gather f,i,g,o for own qubit.
        abf[lane] = a;
        __syncwarp();
        float fv = abf[n];
        float iv = abf[n + 8];
        float gv = abf[n + 16];
        float ov = abf[n + 24];

        cx = fmaf(fv, cx, iv * gv);

        // hx = ov * tanh(cx);  tanh(x) = 2*sigmoid(2x)-1
        float e2 = ex2_approx(cx * (-2.0f * L2E));
        float r2 = rcp_approx(1.0f + e2);
        hx = ov * fmaf(2.0f, r2, -1.0f);

        // Exchange 3: broadcast hx vector for next step's matvec.
        if (lane < 8) hb[lane] = hx;
        __syncwarp();
        float4 h0 = *reinterpret_cast<const float4*>(hb);
        float4 h1 = *reinterpret_cast<const float4*>(hb + 4);
        hxa[0] = h0.x; hxa[1] = h0.y; hxa[2] = h0.z; hxa[3] = h0.w;
        hxa[4] = h1.x; hxa[5] = h1.y; hxa[6] = h1.z; hxa[7] = h1.w;

        if (lane < 8) ob[t * 8] = hx;
        p0 = p1; p1 = p2;
    }

    if (lane < 8) {
        out[2097152 + b * 8 + n] = hx;           // final hx
        out[2097152 + 4096 + b * 8 + n] = cx;    // final cx
    }
}

// ---------------------------------------------------------------------------
extern "C" void kernel_launch(void* const* d_in, const int* in_sizes, int n_in,
                              void* d_out, int out_size) {
    const float* X  = (const float*)d_in[0];
    const float* Wf = (const float*)d_in[1];
    const float* bf = (const float*)d_in[2];
    const float* Wi = (const float*)d_in[3];
    const float* bi = (const float*)d_in[4];
    const float* Wg = (const float*)d_in[5];
    const float* bg = (const float*)d_in[6];
    const float* Wo = (const float*)d_in[7];
    const float* bo = (const float*)d_in[8];
    const float* th = (const float*)d_in[9];
    float* out = (float*)d_out;

    cudaFuncSetAttribute(gemm_kernel,
                         cudaFuncAttributeMaxDynamicSharedMemorySize, SMEM_G);

    gemm_kernel<<<1024, 256, SMEM_G>>>(X, Wf, bf, Wi, bi, Wg, bg, Wo, bo, th);
    recur_kernel<<<128, 128>>>(Wf, Wi, Wg, Wo, out);
}